// round 5
// baseline (speedup 1.0000x reference)
#include <cuda_runtime.h>
#include <cuda_bf16.h>
#include <cstdint>

#define BB   512
#define CC   3
#define TT   500
#define DD   40
#define CD   120
#define NN   256
#define OUTN 12
#define BN   (BB*NN)        // 131072
#define SW   (BN/32)        // 4096 bit-words per timestep
#define B_J0 0.01f
#define BETA 1.8f

// ------------------------- device scratch (allocation-guard-safe) -----------
__device__ float    g_i1[(size_t)TT * BB * NN];     // 262 MB (i1, then reused as i2in)
__device__ unsigned g_s1[(size_t)TT * SW];          // 8.2 MB
__device__ float    g_W2inTp[NN * NN];              // [j][n] scalar transposed
__device__ float2   g_W2recT[NN * 128];             // [j][pair(l, l+128)]
__device__ float    g_acc[BB * OUTN];

// ------------------------- packed f32x2 helpers -----------------------------
__device__ __forceinline__ unsigned long long pack_dup(float a) {
    unsigned long long r;
    asm("mov.b64 %0, {%1,%1};" : "=l"(r) : "f"(a));
    return r;
}
__device__ __forceinline__ void unpack2(unsigned long long v, float& a, float& b) {
    asm("mov.b64 {%0,%1}, %2;" : "=f"(a), "=f"(b) : "l"(v));
}
__device__ __forceinline__ void fma2(unsigned long long& acc,
                                     unsigned long long a, unsigned long long b) {
    asm("fma.rn.f32x2 %0, %1, %2, %0;" : "+l"(acc) : "l"(a), "l"(b));
}

// ------------------------- K0: transpose W2 matrices ------------------------
__global__ void k0_transpose(const float* __restrict__ W2_in,
                             const float* __restrict__ W2_rec)
{
    int j = blockIdx.x;        // presyn 0..255
    int n = threadIdx.x;       // postsyn 0..255
    g_W2inTp[j * NN + n] = W2_in[n * NN + j];
    if (n < 128)
        g_W2recT[j * 128 + n] = make_float2(W2_rec[n * NN + j], W2_rec[(n + 128) * NN + j]);
}

// ------------------------- K1: spikify + i1 GEMM ----------------------------
// grid 4000 blocks x 256 threads. Block: 64 rows (one t, b0..b0+63) x 256 n.
#define K1_SMEM (CD*NN*4 + CD*64*8 + 64*121*4)
__global__ void __launch_bounds__(256, 1)
k1_gemm1(const float* __restrict__ x, const float* __restrict__ thrp,
         const float* __restrict__ W1, const float* __restrict__ b1)
{
    extern __shared__ float sm[];
    float*              w1t   = sm;                                  // [k][n]
    unsigned long long* xs2   = (unsigned long long*)(sm + CD * NN); // [k][r] dup
    float*              stage = (float*)(xs2 + CD * 64);             // [r][121]

    const int tid = threadIdx.x;
    const int p0  = blockIdx.x * 64;
    const int t   = p0 >> 9;
    const int b0  = p0 & 511;
    const float thr = *thrp;

    {
        const int n = tid;
        const float4* wr = (const float4*)(W1 + n * CD);
        #pragma unroll 5
        for (int q = 0; q < 30; q++) {
            float4 v = wr[q];
            int k = q * 4;
            w1t[(k + 0) * NN + n] = v.x;
            w1t[(k + 1) * NN + n] = v.y;
            w1t[(k + 2) * NN + n] = v.z;
            w1t[(k + 3) * NN + n] = v.w;
        }
    }
    for (int i = tid; i < 64 * CD; i += 256) {
        int r  = i / CD;
        int cd = i % CD;
        int c  = cd / DD, d = cd % DD;
        int b  = b0 + r;
        float xv = x[(((size_t)b * CC + c) * TT + t) * DD + d];
        float s  = (xv > thr) ? 1.0f : ((xv < -thr) ? -1.0f : 0.0f);
        stage[r * 121 + cd] = s;
    }
    __syncthreads();
    for (int i = tid; i < CD * 64; i += 256) {
        int cd = i >> 6;
        int r  = i & 63;
        xs2[cd * 64 + r] = pack_dup(stage[r * 121 + cd]);
    }
    __syncthreads();

    const int ng = tid & 31;
    const int rg = tid >> 5;
    unsigned long long acc[32];
    #pragma unroll
    for (int i = 0; i < 32; i++) acc[i] = 0ull;

    #pragma unroll 2
    for (int k = 0; k < CD; k++) {
        const ulonglong2* wp = (const ulonglong2*)(w1t + k * NN + (ng << 3));
        ulonglong2 wA = wp[0];
        ulonglong2 wB = wp[1];
        const ulonglong2* xp = (const ulonglong2*)(xs2 + k * 64 + (rg << 3));
        ulonglong2 x01 = xp[0], x23 = xp[1], x45 = xp[2], x67 = xp[3];
        unsigned long long xd[8] = {x01.x, x01.y, x23.x, x23.y,
                                    x45.x, x45.y, x67.x, x67.y};
        #pragma unroll
        for (int rr = 0; rr < 8; rr++) {
            fma2(acc[rr * 4 + 0], xd[rr], wA.x);
            fma2(acc[rr * 4 + 1], xd[rr], wA.y);
            fma2(acc[rr * 4 + 2], xd[rr], wB.x);
            fma2(acc[rr * 4 + 3], xd[rr], wB.y);
        }
    }

    float4 bq0 = *(const float4*)(b1 + (ng << 3));
    float4 bq1 = *(const float4*)(b1 + (ng << 3) + 4);
    #pragma unroll
    for (int rr = 0; rr < 8; rr++) {
        float o[8];
        #pragma unroll
        for (int np = 0; np < 4; np++)
            unpack2(acc[rr * 4 + np], o[2 * np], o[2 * np + 1]);
        o[0] += bq0.x; o[1] += bq0.y; o[2] += bq0.z; o[3] += bq0.w;
        o[4] += bq1.x; o[5] += bq1.y; o[6] += bq1.z; o[7] += bq1.w;
        size_t base = (size_t)t * BN + (size_t)(b0 + rg * 8 + rr) * NN + (ng << 3);
        *(float4*)&g_i1[base]     = make_float4(o[0], o[1], o[2], o[3]);
        *(float4*)&g_i1[base + 4] = make_float4(o[4], o[5], o[6], o[7]);
    }
}

// ------------------------- K2: layer-1 ALIF scan -> s1 bits -----------------
__global__ void __launch_bounds__(256)
k2_scan1(const float* __restrict__ tau_adp1, const float* __restrict__ tau_m1)
{
    const int gid  = blockIdx.x * 256 + threadIdx.x;
    const int nidx = gid & 255;
    const int lane = threadIdx.x & 31;
    const unsigned wordIdx = gid >> 5;

    const float alpha = __expf(-1.0f / tau_m1[nidx]);
    const float rho   = __expf(-1.0f / tau_adp1[nidx]);
    const float ca = 1.0f - alpha, cr = 1.0f - rho;

    float m = 0.f, a = B_J0, s = 0.f;
    const float* ip = g_i1 + gid;

    for (int t = 0; t < TT; t += 4) {
        float iv[4];
        #pragma unroll
        for (int k = 0; k < 4; k++) iv[k] = ip[(size_t)(t + k) * BN];
        #pragma unroll
        for (int k = 0; k < 4; k++) {
            a = rho * a + cr * s;
            float Bth = B_J0 + BETA * a;
            m = alpha * m + ca * iv[k] - Bth * s;
            s = (m - Bth > 0.f) ? 1.f : 0.f;
            unsigned bal = __ballot_sync(0xffffffffu, s > 0.5f);
            if (lane == 0) g_s1[(size_t)(t + k) * SW + wordIdx] = bal;
        }
    }
}

// ------------------------- K2.5: i2in = b2 + s1 @ W2_in^T (parallel) --------
// grid 1000 CTAs (h = blockIdx&1 postsyn half, t = blockIdx>>1), 256 threads.
// W2in^T half (128 KB) resident in smem. Per iteration: 2 rows (2p, 2p+1);
// spike words compacted to smem index lists (warp-parallel), then a counted
// gather with 4-way batched conflict-free LDS and IN-ORDER serial adds
// (bitwise-matches the R2 accumulation order). Overwrites g_i1 in place.
#define K25_SMEM (NN*128*4 + 2*256*4 + 16*4)
__global__ void __launch_bounds__(256, 1)
k25_gemm2in(const float* __restrict__ b2_in, const float* __restrict__ b2_rec)
{
    extern __shared__ float sm[];
    float*    w2h   = sm;                          // [j][nl] 256x128
    int*      lst   = (int*)(sm + NN * 128);       // [2][256]
    unsigned* words = (unsigned*)(lst + 512);      // [16]

    const int tid  = threadIdx.x;
    const int h    = blockIdx.x & 1;
    const int t    = blockIdx.x >> 1;
    const int nl   = tid & 127;
    const int slot = tid >> 7;
    const int lane = tid & 31;
    const int wid  = tid >> 5;

    for (int i = tid; i < NN * 128; i += 256)
        w2h[i] = g_W2inTp[(i >> 7) * NN + h * 128 + (i & 127)];
    const float bias = b2_in[h * 128 + nl] + b2_rec[h * 128 + nl];
    __syncthreads();

    const size_t tbase = (size_t)t * BN;
    const unsigned* s1t = g_s1 + (size_t)t * SW;
    const unsigned ltm = (1u << lane) - 1u;

    for (int p = 0; p < 256; p++) {
        if (tid < 16)
            words[tid] = s1t[(size_t)(2 * p + (tid >> 3)) * 8 + (tid & 7)];
        __syncthreads();

        // redundant per-thread popc-prefix for both rows (cheap)
        unsigned w0[8], w1[8];
        #pragma unroll
        for (int w = 0; w < 8; w++) { w0[w] = words[w]; w1[w] = words[8 + w]; }
        int off0[8], off1[8], c0 = 0, c1 = 0;
        #pragma unroll
        for (int w = 0; w < 8; w++) {
            off0[w] = c0; c0 += __popc(w0[w]);
            off1[w] = c1; c1 += __popc(w1[w]);
        }
        // warp wid compacts word wid of each row (ascending j preserved)
        {
            unsigned wd = w0[wid];
            if ((wd >> lane) & 1u)
                lst[off0[wid] + __popc(wd & ltm)] = wid * 32 + lane;
            wd = w1[wid];
            if ((wd >> lane) & 1u)
                lst[256 + off1[wid] + __popc(wd & ltm)] = wid * 32 + lane;
        }
        __syncthreads();

        const int  cnt = slot ? c1 : c0;
        const int* ml  = lst + slot * 256;
        float acc = bias;
        int k = 0;
        for (; k + 4 <= cnt; k += 4) {
            int j0 = ml[k], j1 = ml[k + 1], j2 = ml[k + 2], j3 = ml[k + 3];
            float v0 = w2h[j0 * 128 + nl];
            float v1 = w2h[j1 * 128 + nl];
            float v2 = w2h[j2 * 128 + nl];
            float v3 = w2h[j3 * 128 + nl];
            acc += v0; acc += v1; acc += v2; acc += v3;   // in-order
        }
        for (; k < cnt; k++) acc += w2h[ml[k] * 128 + nl];

        g_i1[tbase + (size_t)(2 * p + slot) * NN + h * 128 + nl] = acc;
        __syncthreads();   // protect words/lst reuse
    }
}

// ------------------------- K3: sequential layer-2(rec) + layer-3 ------------
// R2-proven structure: 512 CTAs x 128 threads (thread l owns n=l and n=l+128).
// s1 term comes precomputed from g_i1 (i2in) with 1-step register prefetch;
// only the s2 recurrent gather (list-compacted, 4-way batched LDG.64) remains.
__global__ void __launch_bounds__(128)
k3_recurrent(const float* __restrict__ W3, const float* __restrict__ b3,
             const float* __restrict__ tau_adp2, const float* __restrict__ tau_m2,
             const float* __restrict__ tau_m3)
{
    __shared__ float    W3s[OUTN * 257];
    __shared__ unsigned words[8];     // prev-step s2 ballots
    __shared__ int      lst2[256];

    const int b    = blockIdx.x;
    const int l    = threadIdx.x;
    const int lane = l & 31;
    const int wid  = l >> 5;

    for (int i = l; i < OUTN * NN; i += 128)
        W3s[(i >> 8) * 257 + (i & 255)] = W3[i];
    if (l < 8) words[l] = 0u;

    const int n0 = l, n1 = l + 128;
    const float al_a = __expf(-1.0f / tau_m2[n0]),   al_b = __expf(-1.0f / tau_m2[n1]);
    const float rh_a = __expf(-1.0f / tau_adp2[n0]), rh_b = __expf(-1.0f / tau_adp2[n1]);

    float m2a = 0.f, m2b = 0.f, a2a = B_J0, a2b = B_J0, s2a = 0.f, s2b = 0.f;

    float al3 = 1.f, m3 = 0.f, accr = 0.f, b3v = 0.f;
    if (l < OUTN) { al3 = __expf(-1.0f / tau_m3[l]); b3v = b3[l]; }

    const float2* __restrict__ w2r = g_W2recT;
    const float*  __restrict__ i2p = g_i1 + (size_t)b * NN + l;
    const unsigned ltm = (1u << lane) - 1u;

    __syncthreads();

    float iva = i2p[0], ivb = i2p[128];     // t = 0

    for (int t = 0; t < TT; t++) {
        __syncthreads();   // prev ballots visible; lst2 free

        // prefetch next step's i2in
        float nva, nvb;
        {
            int tn = (t + 1 < TT) ? (t + 1) : t;
            nva = i2p[(size_t)tn * BN];
            nvb = i2p[(size_t)tn * BN + 128];
        }

        // deferred layer-3 for step t-1 (warp-0 lanes 0..11)
        if (l < OUTN && t > 0) {
            float i3 = b3v;
            const float* wr = &W3s[l * 257];
            #pragma unroll
            for (int w = 0; w < 8; w++) {
                unsigned m = words[w];
                int base = w * 32;
                while (m) {
                    int j = __ffs((int)m) - 1;
                    m &= m - 1;
                    i3 += wr[base + j];
                }
            }
            m3 = al3 * m3 + (1.0f - al3) * i3;
            accr += m3;
        }

        // compaction of s2 words into lst2 (ascending j)
        unsigned wv[8];
        #pragma unroll
        for (int w = 0; w < 8; w++) wv[w] = words[w];
        int off[8], cnt2 = 0;
        #pragma unroll
        for (int w = 0; w < 8; w++) { off[w] = cnt2; cnt2 += __popc(wv[w]); }
        #pragma unroll
        for (int g = 0; g < 2; g++) {
            int w = wid + g * 4;
            unsigned wd = wv[w];
            if ((wd >> lane) & 1u)
                lst2[off[w] + __popc(wd & ltm)] = w * 32 + lane;
        }
        __syncthreads();   // lists ready

        // gather (4-way batched loads, in-order adds)
        float i2a = iva, i2b = ivb;
        {
            int k = 0;
            for (; k + 4 <= cnt2; k += 4) {
                int j0 = lst2[k], j1 = lst2[k + 1], j2 = lst2[k + 2], j3 = lst2[k + 3];
                float2 v0 = w2r[j0 * 128 + l];
                float2 v1 = w2r[j1 * 128 + l];
                float2 v2 = w2r[j2 * 128 + l];
                float2 v3 = w2r[j3 * 128 + l];
                i2a += v0.x; i2b += v0.y;
                i2a += v1.x; i2b += v1.y;
                i2a += v2.x; i2b += v2.y;
                i2a += v3.x; i2b += v3.y;
            }
            for (; k < cnt2; k++) {
                int j = lst2[k];
                float2 v = w2r[j * 128 + l];
                i2a += v.x; i2b += v.y;
            }
        }

        // ALIF update
        a2a = rh_a * a2a + (1.0f - rh_a) * s2a;
        a2b = rh_b * a2b + (1.0f - rh_b) * s2b;
        float Ba = B_J0 + BETA * a2a;
        float Bb = B_J0 + BETA * a2b;
        m2a = al_a * m2a + (1.0f - al_a) * i2a - Ba * s2a;
        m2b = al_b * m2b + (1.0f - al_b) * i2b - Bb * s2b;
        s2a = (m2a - Ba > 0.f) ? 1.f : 0.f;
        s2b = (m2b - Bb > 0.f) ? 1.f : 0.f;

        unsigned bala = __ballot_sync(0xffffffffu, s2a > 0.5f);
        unsigned balb = __ballot_sync(0xffffffffu, s2b > 0.5f);
        if (lane == 0) {
            words[wid]     = bala;
            words[4 + wid] = balb;
        }
        iva = nva; ivb = nvb;
    }

    // final deferred layer-3 (step TT-1)
    __syncthreads();
    if (l < OUTN) {
        float i3 = b3v;
        const float* wr = &W3s[l * 257];
        #pragma unroll
        for (int w = 0; w < 8; w++) {
            unsigned m = words[w];
            int base = w * 32;
            while (m) {
                int j = __ffs((int)m) - 1;
                m &= m - 1;
                i3 += wr[base + j];
            }
        }
        m3 = al3 * m3 + (1.0f - al3) * i3;
        accr += m3;
        g_acc[b * OUTN + l] = accr;
    }
}

// ------------------------- K4: log-softmax ----------------------------------
__global__ void __launch_bounds__(256)
k4_softmax(float* __restrict__ out)
{
    int b = blockIdx.x * 256 + threadIdx.x;
    if (b >= BB) return;
    float v[OUTN];
    float mx = -1e30f;
    #pragma unroll
    for (int o = 0; o < OUTN; o++) {
        v[o] = g_acc[b * OUTN + o] * (1.0f / (float)TT);
        mx = fmaxf(mx, v[o]);
    }
    float sum = 0.f;
    #pragma unroll
    for (int o = 0; o < OUTN; o++) sum += __expf(v[o] - mx);
    float lse = mx + __logf(sum);
    #pragma unroll
    for (int o = 0; o < OUTN; o++) out[b * OUTN + o] = v[o] - lse;
}

// ------------------------- launch -------------------------------------------
extern "C" void kernel_launch(void* const* d_in, const int* in_sizes, int n_in,
                              void* d_out, int out_size)
{
    const float* x        = (const float*)d_in[0];
    const float* thr      = (const float*)d_in[1];
    const float* W1       = (const float*)d_in[2];
    const float* b1       = (const float*)d_in[3];
    const float* W2_in    = (const float*)d_in[4];
    const float* b2_in    = (const float*)d_in[5];
    const float* W2_rec   = (const float*)d_in[6];
    const float* b2_rec   = (const float*)d_in[7];
    const float* W3       = (const float*)d_in[8];
    const float* b3       = (const float*)d_in[9];
    const float* tau_adp1 = (const float*)d_in[10];
    const float* tau_m1   = (const float*)d_in[11];
    const float* tau_adp2 = (const float*)d_in[12];
    const float* tau_m2   = (const float*)d_in[13];
    const float* tau_m3   = (const float*)d_in[14];
    float* out = (float*)d_out;

    cudaFuncSetAttribute(k1_gemm1,    cudaFuncAttributeMaxDynamicSharedMemorySize, K1_SMEM);
    cudaFuncSetAttribute(k25_gemm2in, cudaFuncAttributeMaxDynamicSharedMemorySize, K25_SMEM);

    k0_transpose<<<NN, NN>>>(W2_in, W2_rec);
    k1_gemm1<<<(TT * BB) / 64, 256, K1_SMEM>>>(x, thr, W1, b1);
    k2_scan1<<<BB, 256>>>(tau_adp1, tau_m1);
    k25_gemm2in<<<2 * TT, 256, K25_SMEM>>>(b2_in, b2_rec);
    k3_recurrent<<<BB, 128>>>(W3, b3, tau_adp2, tau_m2, tau_m3);
    k4_softmax<<<(BB + 255) / 256, 256>>>(out);
}

// round 6
// speedup vs baseline: 1.9888x; 1.9888x over previous
#include <cuda_runtime.h>
#include <cuda_bf16.h>
#include <cstdint>

#define BB   512
#define CC   3
#define TT   500
#define DD   40
#define CD   120
#define NN   256
#define OUTN 12
#define BN   (BB*NN)        // 131072
#define B_J0 0.01f
#define BETA 1.8f

// ------------------------- device scratch (allocation-guard-safe) -----------
__device__ float         g_i1[(size_t)TT * BB * NN];   // 262 MB (i1, then i2in)
__device__ unsigned char g_lst[(size_t)TT * BB * 256]; // 65.5 MB s1 index lists
__device__ int           g_cnt[TT * BB];               // list lengths
__device__ float         g_W2inQ[4 * 256 * 64];        // [q][j][nl] quarters
__device__ float         g_W2recTp[NN * NN];           // [j][n]
__device__ float         g_acc[BB * OUTN];

// ------------------------- packed f32x2 helpers -----------------------------
__device__ __forceinline__ unsigned long long pack_dup(float a) {
    unsigned long long r;
    asm("mov.b64 %0, {%1,%1};" : "=l"(r) : "f"(a));
    return r;
}
__device__ __forceinline__ void unpack2(unsigned long long v, float& a, float& b) {
    asm("mov.b64 {%0,%1}, %2;" : "=f"(a), "=f"(b) : "l"(v));
}
__device__ __forceinline__ void fma2(unsigned long long& acc,
                                     unsigned long long a, unsigned long long b) {
    asm("fma.rn.f32x2 %0, %1, %2, %0;" : "+l"(acc) : "l"(a), "l"(b));
}

// ------------------------- K0: weight layout prep ---------------------------
__global__ void k0_prep(const float* __restrict__ W2_in,
                        const float* __restrict__ W2_rec)
{
    int j = blockIdx.x;        // presyn 0..255
    int n = threadIdx.x;       // postsyn 0..255
    g_W2recTp[j * NN + n] = W2_rec[n * NN + j];
    g_W2inQ[(((n >> 6) * 256) + j) * 64 + (n & 63)] = W2_in[n * NN + j];
}

// ------------------------- K1: spikify + i1 GEMM ----------------------------
#define K1_SMEM (CD*NN*4 + CD*64*8 + 64*121*4)
__global__ void __launch_bounds__(256, 1)
k1_gemm1(const float* __restrict__ x, const float* __restrict__ thrp,
         const float* __restrict__ W1, const float* __restrict__ b1)
{
    extern __shared__ float sm[];
    float*              w1t   = sm;                                  // [k][n]
    unsigned long long* xs2   = (unsigned long long*)(sm + CD * NN); // [k][r] dup
    float*              stage = (float*)(xs2 + CD * 64);             // [r][121]

    const int tid = threadIdx.x;
    const int p0  = blockIdx.x * 64;
    const int t   = p0 >> 9;
    const int b0  = p0 & 511;
    const float thr = *thrp;

    {
        const int n = tid;
        const float4* wr = (const float4*)(W1 + n * CD);
        #pragma unroll 5
        for (int q = 0; q < 30; q++) {
            float4 v = wr[q];
            int k = q * 4;
            w1t[(k + 0) * NN + n] = v.x;
            w1t[(k + 1) * NN + n] = v.y;
            w1t[(k + 2) * NN + n] = v.z;
            w1t[(k + 3) * NN + n] = v.w;
        }
    }
    for (int i = tid; i < 64 * CD; i += 256) {
        int r  = i / CD;
        int cd = i % CD;
        int c  = cd / DD, d = cd % DD;
        int b  = b0 + r;
        float xv = x[(((size_t)b * CC + c) * TT + t) * DD + d];
        float s  = (xv > thr) ? 1.0f : ((xv < -thr) ? -1.0f : 0.0f);
        stage[r * 121 + cd] = s;
    }
    __syncthreads();
    for (int i = tid; i < CD * 64; i += 256) {
        int cd = i >> 6;
        int r  = i & 63;
        xs2[cd * 64 + r] = pack_dup(stage[r * 121 + cd]);
    }
    __syncthreads();

    const int ng = tid & 31;
    const int rg = tid >> 5;
    unsigned long long acc[32];
    #pragma unroll
    for (int i = 0; i < 32; i++) acc[i] = 0ull;

    #pragma unroll 2
    for (int k = 0; k < CD; k++) {
        const ulonglong2* wp = (const ulonglong2*)(w1t + k * NN + (ng << 3));
        ulonglong2 wA = wp[0];
        ulonglong2 wB = wp[1];
        const ulonglong2* xp = (const ulonglong2*)(xs2 + k * 64 + (rg << 3));
        ulonglong2 x01 = xp[0], x23 = xp[1], x45 = xp[2], x67 = xp[3];
        unsigned long long xd[8] = {x01.x, x01.y, x23.x, x23.y,
                                    x45.x, x45.y, x67.x, x67.y};
        #pragma unroll
        for (int rr = 0; rr < 8; rr++) {
            fma2(acc[rr * 4 + 0], xd[rr], wA.x);
            fma2(acc[rr * 4 + 1], xd[rr], wA.y);
            fma2(acc[rr * 4 + 2], xd[rr], wB.x);
            fma2(acc[rr * 4 + 3], xd[rr], wB.y);
        }
    }

    float4 bq0 = *(const float4*)(b1 + (ng << 3));
    float4 bq1 = *(const float4*)(b1 + (ng << 3) + 4);
    #pragma unroll
    for (int rr = 0; rr < 8; rr++) {
        float o[8];
        #pragma unroll
        for (int np = 0; np < 4; np++)
            unpack2(acc[rr * 4 + np], o[2 * np], o[2 * np + 1]);
        o[0] += bq0.x; o[1] += bq0.y; o[2] += bq0.z; o[3] += bq0.w;
        o[4] += bq1.x; o[5] += bq1.y; o[6] += bq1.z; o[7] += bq1.w;
        size_t base = (size_t)t * BN + (size_t)(b0 + rg * 8 + rr) * NN + (ng << 3);
        *(float4*)&g_i1[base]     = make_float4(o[0], o[1], o[2], o[3]);
        *(float4*)&g_i1[base + 4] = make_float4(o[4], o[5], o[6], o[7]);
    }
}

// ------------------------- K2: layer-1 ALIF scan -> compacted s1 lists ------
// block = one batch b, 256 threads = neurons. Per step: ballot, block-wide
// popc-prefix, scatter ascending-j u8 indices to g_lst + count to g_cnt.
__global__ void __launch_bounds__(256)
k2_scan1(const float* __restrict__ tau_adp1, const float* __restrict__ tau_m1)
{
    __shared__ unsigned swords[2][8];

    const int b    = blockIdx.x;
    const int tid  = threadIdx.x;
    const int n    = tid;
    const int lane = tid & 31;
    const int wid  = tid >> 5;
    const unsigned ltm = (1u << lane) - 1u;

    const float alpha = __expf(-1.0f / tau_m1[n]);
    const float rho   = __expf(-1.0f / tau_adp1[n]);
    const float ca = 1.0f - alpha, cr = 1.0f - rho;

    float m = 0.f, a = B_J0, s = 0.f;
    const float* ip = g_i1 + (size_t)b * NN + n;

    for (int t4 = 0; t4 < TT; t4 += 4) {
        float iv[4];
        #pragma unroll
        for (int k = 0; k < 4; k++) iv[k] = ip[(size_t)(t4 + k) * BN];
        #pragma unroll
        for (int k = 0; k < 4; k++) {
            const int t = t4 + k;
            a = rho * a + cr * s;
            float Bth = B_J0 + BETA * a;
            m = alpha * m + ca * iv[k] - Bth * s;
            s = (m - Bth > 0.f) ? 1.f : 0.f;
            unsigned bal = __ballot_sync(0xffffffffu, s > 0.5f);
            if (lane == 0) swords[t & 1][wid] = bal;
            __syncthreads();
            unsigned wv[8];
            #pragma unroll
            for (int w = 0; w < 8; w++) wv[w] = swords[t & 1][w];
            int off = 0, myoff = 0;
            #pragma unroll
            for (int w = 0; w < 8; w++) {
                if (w == wid) myoff = off;
                off += __popc(wv[w]);
            }
            unsigned wd = wv[wid];
            if ((wd >> lane) & 1u)
                g_lst[(size_t)(t * BB + b) * 256 + myoff + __popc(wd & ltm)] =
                    (unsigned char)(wid * 32 + lane);
            if (tid == 0) g_cnt[t * BB + b] = off;
        }
    }
}

// ------------------------- K2.5: i2in = b2 + s1 @ W2_in^T -------------------
// grid 4000: q = n-quarter, bh = batch half, t. 64KB weight quarter in smem
// (2 CTAs/SM). Warp-autonomous: each warp owns 32 rows, double-buffers the
// index list one row ahead (syncwarp only). Ascending-j in-order adds.
#define K25_SMEM (64*1024 + 8*2*64*4)
__global__ void __launch_bounds__(256, 2)
k25_gemm2in(const float* __restrict__ b2_in, const float* __restrict__ b2_rec)
{
    extern __shared__ float sm[];
    float2*   w2  = (float2*)sm;                  // [j*32+lane] pairs
    unsigned* lsb = (unsigned*)(sm + 16384);      // [8 warps][2][64]

    const int idx  = blockIdx.x;
    const int q    = idx & 3;
    const int bh   = (idx >> 2) & 1;
    const int t    = idx >> 3;
    const int tid  = threadIdx.x;
    const int lane = tid & 31;
    const int wid  = tid >> 5;

    {
        const float4* src = (const float4*)(g_W2inQ + q * 256 * 64);
        float4* dst = (float4*)sm;
        for (int i = tid; i < 4096; i += 256) dst[i] = src[i];
    }
    const int n0 = q * 64 + lane * 2;
    const float2 bias2 = make_float2(b2_in[n0] + b2_rec[n0],
                                     b2_in[n0 + 1] + b2_rec[n0 + 1]);
    __syncthreads();

    const int bbase = bh * 256 + wid * 32;
    const int cb    = t * BB + bbase;
    const int mycnt = g_cnt[cb + lane];          // lane i -> row i count
    unsigned* mybuf = lsb + wid * 128;           // [2][64]

    // prologue: stage row 0's list
    {
        int c0  = __shfl_sync(0xffffffffu, mycnt, 0);
        int nch = (c0 + 15) >> 4;
        if (lane < nch) {
            uint4 v = ((const uint4*)(g_lst + (size_t)cb * 256))[lane];
            unsigned* d = mybuf + lane * 4;
            d[0] = v.x; d[1] = v.y; d[2] = v.z; d[3] = v.w;
        }
        __syncwarp();
    }

    for (int i = 0; i < 32; i++) {
        // prefetch next row's list into registers (non-blocking)
        uint4 vn = make_uint4(0, 0, 0, 0);
        int nchn = 0;
        if (i + 1 < 32) {
            int cn = __shfl_sync(0xffffffffu, mycnt, i + 1);
            nchn = (cn + 15) >> 4;
            if (lane < nchn)
                vn = ((const uint4*)(g_lst + (size_t)(cb + i + 1) * 256))[lane];
        }
        const int cnt = __shfl_sync(0xffffffffu, mycnt, i);
        const unsigned* lb = mybuf + (i & 1) * 64;

        float2 acc = bias2;
        int k = 0;
        for (; k + 4 <= cnt; k += 4) {
            unsigned w = lb[k >> 2];
            int j0 = w & 255, j1 = (w >> 8) & 255, j2 = (w >> 16) & 255, j3 = w >> 24;
            float2 v0 = w2[j0 * 32 + lane];
            float2 v1 = w2[j1 * 32 + lane];
            float2 v2 = w2[j2 * 32 + lane];
            float2 v3 = w2[j3 * 32 + lane];
            acc.x += v0.x; acc.y += v0.y;
            acc.x += v1.x; acc.y += v1.y;
            acc.x += v2.x; acc.y += v2.y;
            acc.x += v3.x; acc.y += v3.y;
        }
        if (k < cnt) {
            unsigned w = lb[k >> 2];
            for (; k < cnt; k++) {
                int j = (w >> (8 * (k & 3))) & 255;
                float2 v = w2[j * 32 + lane];
                acc.x += v.x; acc.y += v.y;
            }
        }

        ((float2*)(g_i1 + (size_t)t * BN + (size_t)(bbase + i) * NN + q * 64))[lane] = acc;

        if (i + 1 < 32 && lane < nchn) {
            unsigned* d = mybuf + ((i + 1) & 1) * 64 + lane * 4;
            d[0] = vn.x; d[1] = vn.y; d[2] = vn.z; d[3] = vn.w;
        }
        __syncwarp();
    }
}

// ------------------------- K3: sequential layer-2(rec) + layer-3 ------------
// 512 CTAs x 256 threads (1 neuron per thread -> 27 warps/SM). i2in streamed
// with register prefetch; s2 gather list-compacted, 8-way batched LDG.32.
__global__ void __launch_bounds__(256)
k3_recurrent(const float* __restrict__ W3, const float* __restrict__ b3,
             const float* __restrict__ tau_adp2, const float* __restrict__ tau_m2,
             const float* __restrict__ tau_m3)
{
    __shared__ float    W3s[OUTN * 257];
    __shared__ unsigned words[8];
    __shared__ int      lst2[256];

    const int b    = blockIdx.x;
    const int tid  = threadIdx.x;
    const int n    = tid;
    const int lane = tid & 31;
    const int wid  = tid >> 5;
    const unsigned ltm = (1u << lane) - 1u;

    for (int i = tid; i < OUTN * NN; i += 256)
        W3s[(i >> 8) * 257 + (i & 255)] = W3[i];
    if (tid < 8) words[tid] = 0u;

    const float al = __expf(-1.0f / tau_m2[n]);
    const float rh = __expf(-1.0f / tau_adp2[n]);
    float m2 = 0.f, a2 = B_J0, s2 = 0.f;

    float al3 = 1.f, m3 = 0.f, accr = 0.f, b3v = 0.f;
    if (tid < OUTN) { al3 = __expf(-1.0f / tau_m3[tid]); b3v = b3[tid]; }

    const float* __restrict__ w2rf = g_W2recTp;
    const float* __restrict__ i2p  = g_i1 + (size_t)b * NN + n;

    __syncthreads();

    float iv = i2p[0];

    for (int t = 0; t < TT; t++) {
        __syncthreads();   // prev ballots visible; lst2 free

        const int tn = (t + 1 < TT) ? (t + 1) : t;
        float nv = i2p[(size_t)tn * BN];

        // deferred layer-3 for step t-1 (warp-0 lanes 0..11)
        if (tid < OUTN && t > 0) {
            float i3 = b3v;
            const float* wr = &W3s[tid * 257];
            #pragma unroll
            for (int w = 0; w < 8; w++) {
                unsigned mm = words[w];
                int base = w * 32;
                while (mm) {
                    int j = __ffs((int)mm) - 1;
                    mm &= mm - 1;
                    i3 += wr[base + j];
                }
            }
            m3 = al3 * m3 + (1.0f - al3) * i3;
            accr += m3;
        }

        // compaction (ascending j)
        unsigned wv[8];
        #pragma unroll
        for (int w = 0; w < 8; w++) wv[w] = words[w];
        int off = 0, myoff = 0;
        #pragma unroll
        for (int w = 0; w < 8; w++) {
            if (w == wid) myoff = off;
            off += __popc(wv[w]);
        }
        const int cnt2 = off;
        unsigned wd = wv[wid];
        if ((wd >> lane) & 1u)
            lst2[myoff + __popc(wd & ltm)] = wid * 32 + lane;
        __syncthreads();   // lists ready

        // gather: 8-way batched independent LDG.32, in-order adds
        float i2 = iv;
        {
            int k = 0;
            for (; k + 8 <= cnt2; k += 8) {
                int j0 = lst2[k],     j1 = lst2[k + 1], j2 = lst2[k + 2], j3 = lst2[k + 3];
                int j4 = lst2[k + 4], j5 = lst2[k + 5], j6 = lst2[k + 6], j7 = lst2[k + 7];
                float v0 = w2rf[j0 * NN + n];
                float v1 = w2rf[j1 * NN + n];
                float v2 = w2rf[j2 * NN + n];
                float v3 = w2rf[j3 * NN + n];
                float v4 = w2rf[j4 * NN + n];
                float v5 = w2rf[j5 * NN + n];
                float v6 = w2rf[j6 * NN + n];
                float v7 = w2rf[j7 * NN + n];
                i2 += v0; i2 += v1; i2 += v2; i2 += v3;
                i2 += v4; i2 += v5; i2 += v6; i2 += v7;
            }
            for (; k < cnt2; k++) i2 += w2rf[lst2[k] * NN + n];
        }

        // ALIF update
        a2 = rh * a2 + (1.0f - rh) * s2;
        float Bth = B_J0 + BETA * a2;
        m2 = al * m2 + (1.0f - al) * i2 - Bth * s2;
        s2 = (m2 - Bth > 0.f) ? 1.f : 0.f;

        unsigned bal = __ballot_sync(0xffffffffu, s2 > 0.5f);
        if (lane == 0) words[wid] = bal;
        iv = nv;
    }

    // final deferred layer-3 (step TT-1)
    __syncthreads();
    if (tid < OUTN) {
        float i3 = b3v;
        const float* wr = &W3s[tid * 257];
        #pragma unroll
        for (int w = 0; w < 8; w++) {
            unsigned mm = words[w];
            int base = w * 32;
            while (mm) {
                int j = __ffs((int)mm) - 1;
                mm &= mm - 1;
                i3 += wr[base + j];
            }
        }
        m3 = al3 * m3 + (1.0f - al3) * i3;
        accr += m3;
        g_acc[b * OUTN + tid] = accr;
    }
}

// ------------------------- K4: log-softmax ----------------------------------
__global__ void __launch_bounds__(256)
k4_softmax(float* __restrict__ out)
{
    int b = blockIdx.x * 256 + threadIdx.x;
    if (b >= BB) return;
    float v[OUTN];
    float mx = -1e30f;
    #pragma unroll
    for (int o = 0; o < OUTN; o++) {
        v[o] = g_acc[b * OUTN + o] * (1.0f / (float)TT);
        mx = fmaxf(mx, v[o]);
    }
    float sum = 0.f;
    #pragma unroll
    for (int o = 0; o < OUTN; o++) sum += __expf(v[o] - mx);
    float lse = mx + __logf(sum);
    #pragma unroll
    for (int o = 0; o < OUTN; o++) out[b * OUTN + o] = v[o] - lse;
}

// ------------------------- launch -------------------------------------------
extern "C" void kernel_launch(void* const* d_in, const int* in_sizes, int n_in,
                              void* d_out, int out_size)
{
    const float* x        = (const float*)d_in[0];
    const float* thr      = (const float*)d_in[1];
    const float* W1       = (const float*)d_in[2];
    const float* b1       = (const float*)d_in[3];
    const float* W2_in    = (const float*)d_in[4];
    const float* b2_in    = (const float*)d_in[5];
    const float* W2_rec   = (const float*)d_in[6];
    const float* b2_rec   = (const float*)d_in[7];
    const float* W3       = (const float*)d_in[8];
    const float* b3       = (const float*)d_in[9];
    const float* tau_adp1 = (const float*)d_in[10];
    const float* tau_m1   = (const float*)d_in[11];
    const float* tau_adp2 = (const float*)d_in[12];
    const float* tau_m2   = (const float*)d_in[13];
    const float* tau_m3   = (const float*)d_in[14];
    float* out = (float*)d_out;

    cudaFuncSetAttribute(k1_gemm1,    cudaFuncAttributeMaxDynamicSharedMemorySize, K1_SMEM);
    cudaFuncSetAttribute(k25_gemm2in, cudaFuncAttributeMaxDynamicSharedMemorySize, K25_SMEM);

    k0_prep<<<NN, NN>>>(W2_in, W2_rec);
    k1_gemm1<<<(TT * BB) / 64, 256, K1_SMEM>>>(x, thr, W1, b1);
    k2_scan1<<<BB, 256>>>(tau_adp1, tau_m1);
    k25_gemm2in<<<8 * TT, 256, K25_SMEM>>>(b2_in, b2_rec);
    k3_recurrent<<<BB, 256>>>(W3, b3, tau_adp2, tau_m2, tau_m3);
    k4_softmax<<<(BB + 255) / 256, 256>>>(out);
}